// round 9
// baseline (speedup 1.0000x reference)
#include <cuda_runtime.h>
#include <cstdint>

#define NHEADS 16
#define OD     1024
#define OF     768        // fp32-exact options [0,768)
#define OI     256        // int8 options [768,1024)
#define KD     128
#define NK4    32
#define NTOK   4096
#define EDIM   2048
#define TM     32         // tokens per main block
#define CWF    96         // fp32 options per iter
#define CWQ    32         // int8 options per iter
#define NIT    8
#define TH     0.032f
#define NEG_INF (-3.402823466e38f)
#define R2CAP  1024

typedef unsigned long long u64;

// ---------------- device scratch ----------------
__device__ __align__(16) float g_wt[(size_t)NHEADS*KD*OD];   // [h][k][o] fp32 transposed (ALL)
__device__ __align__(16) int   g_wq[(size_t)NHEADS*NK4*OI];  // [h][k4][o-768] packed int8
__device__ __align__(16) float g_sw[NHEADS*OI];
__device__ int      g_idx[NTOK*NHEADS];
__device__ unsigned g_r1n;
__device__ uint2    g_r1[NTOK*NHEADS];
__device__ unsigned g_r2n[NHEADS];
__device__ int      g_r2[NHEADS][R2CAP];
__device__ u64      g_best[NTOK*NHEADS];

// ---------------- main-kernel smem (bytes) ----------------
#define SM_XS2 0                        // u64 [128][32] x dup      (32768)
#define SM_WF  32768                    // u64 [128][48] w pairs    (49152)
#define SM_STG SM_WF                    // f32 [32][132] staging (aliases WF, prologue only)
#define SM_WQ  81920                    // int [32][32]             (4096)
#define SM_XQ  86016                    // int [32][32]             (4096)
#define SM_SWS 90112                    // 32 f32
#define SM_SXS 90240                    // 32 f32
#define SM_INV 90368                    // 32 f32
#define SM_TOT 90496

// ---------------- helpers ----------------
#define CP16(dst, src) \
    asm volatile("cp.async.cg.shared.global [%0], [%1], 16;" :: "r"(dst), "l"(src))
#define CPCOMMIT() asm volatile("cp.async.commit_group;" ::: "memory")
#define CPWAIT0()  asm volatile("cp.async.wait_group 0;" ::: "memory")

__device__ __forceinline__ uint32_t smem_u32(const void* p) {
    uint32_t a;
    asm("{ .reg .u64 t; cvta.to.shared.u64 t, %1; cvt.u32.u64 %0, t; }" : "=r"(a) : "l"(p));
    return a;
}
__device__ __forceinline__ u64 pack2(float lo, float hi) {
    u64 r; asm("mov.b64 %0, {%1, %2};" : "=l"(r) : "f"(lo), "f"(hi)); return r;
}
__device__ __forceinline__ void unpack2(u64 v, float &lo, float &hi) {
    asm("mov.b64 {%0, %1}, %2;" : "=f"(lo), "=f"(hi) : "l"(v));
}
__device__ __forceinline__ u64 ffma2(u64 a, u64 b, u64 c) {
    u64 d; asm("fma.rn.f32x2 %0, %1, %2, %3;" : "=l"(d) : "l"(a), "l"(b), "l"(c));
    return d;
}
__device__ __forceinline__ int q8(float v, float inv) {
    int a = __float2int_rn(v * inv);
    return a < -127 ? -127 : (a > 127 ? 127 : a);
}
__device__ __forceinline__ void merge3(float& a1, float& a2, float& a3, int& j1, int& j2,
                                       float b1, float b2, float b3, int k1, int k2) {
    if (b1 > a1 || (b1 == a1 && k1 < j1)) {
        float t1 = a1, t2 = a2, t3 = a3; int u1 = j1, u2 = j2;
        a1 = b1; a2 = b2; a3 = b3; j1 = k1; j2 = k2;
        b1 = t1; b2 = t2; b3 = t3; k1 = u1; k2 = u2;
    }
    if (b1 > a2 || (b1 == a2 && k1 < j2)) { a3 = fmaxf(a2, b2); a2 = b1; j2 = k1; }
    else                                  { a3 = fmaxf(a3, b1); }
}
__device__ __forceinline__ unsigned enc_f(float f) {
    unsigned u = __float_as_uint(f);
    return (u & 0x80000000u) ? ~u : (u | 0x80000000u);
}

// ---------------- w preprocessing ----------------
__global__ __launch_bounds__(256) void prep_w_kernel(const float* __restrict__ w) {
    __shared__ float trf[128 * 33];
    __shared__ float sws_s[32], invs[32];
    if (blockIdx.x == 0 && blockIdx.y == 0) {
        if (threadIdx.x == 0) g_r1n = 0;
        if (threadIdx.x < NHEADS) g_r2n[threadIdx.x] = 0;
    }
    const int h = blockIdx.y, o0 = blockIdx.x * 32;
    const int tid = threadIdx.x, l = tid & 31, wid = tid >> 5;

    for (int r = wid; r < 32; r += 8) {
        float4 v = *(const float4*)(w + ((size_t)h * OD + o0 + r) * KD + l * 4);
        trf[(4*l+0)*33 + r] = v.x; trf[(4*l+1)*33 + r] = v.y;
        trf[(4*l+2)*33 + r] = v.z; trf[(4*l+3)*33 + r] = v.w;
        if (o0 >= OF) {
            float mx = fmaxf(fmaxf(fabsf(v.x), fabsf(v.y)), fmaxf(fabsf(v.z), fabsf(v.w)));
#pragma unroll
            for (int off = 16; off; off >>= 1)
                mx = fmaxf(mx, __shfl_xor_sync(0xffffffffu, mx, off));
            if (l == 0) {
                sws_s[r] = mx * (1.f / 127.f);
                invs[r]  = (mx > 0.f) ? 127.f / mx : 0.f;
            }
        }
    }
    __syncthreads();
    for (int i = tid; i < 4096; i += 256) {
        int k = i >> 5, rl = i & 31;
        g_wt[((size_t)h * KD + k) * OD + o0 + rl] = trf[k * 33 + rl];
    }
    if (o0 >= OF) {
        for (int i = tid; i < 1024; i += 256) {
            int k4 = i >> 5, rl = i & 31;
            float inv = invs[rl];
            int a0 = q8(trf[(4*k4+0)*33 + rl], inv);
            int a1 = q8(trf[(4*k4+1)*33 + rl], inv);
            int a2 = q8(trf[(4*k4+2)*33 + rl], inv);
            int a3 = q8(trf[(4*k4+3)*33 + rl], inv);
            g_wq[((size_t)h * NK4 + k4) * OI + (o0 - OF) + rl] =
                (a0 & 255) | ((a1 & 255) << 8) | ((a2 & 255) << 16) | ((a3 & 255) << 24);
        }
        if (tid < 32) g_sw[h * OI + (o0 - OF) + tid] = sws_s[tid];
    }
}

// ---------------- main hybrid kernel (2 blocks/SM) ----------------
// 256 threads = 16 tx x 16 ty; thread tile = 2 tokens x (6 fp32 + 2 int8) options
__global__ __launch_bounds__(256, 2) void vq_hybrid_kernel(const float* __restrict__ x) {
    extern __shared__ char sm[];
    const uint32_t sb = smem_u32(sm);
    const int tid = threadIdx.x, l = tid & 31, wrp = tid >> 5;
    const int tx = tid & 15, ty = tid >> 4;
    const int t0 = blockIdx.x * TM, h = blockIdx.y;

    const float* wtsrc = g_wt + (size_t)h * KD * OD;
    const int*   wqsrc = g_wq + (size_t)h * NK4 * OI;
    const float* swsrc = g_sw + (size_t)h * OI;

    // ---- prologue pass 1: x rows -> row-major staging (conflict-free) + scales ----
    {
        float* stg = (float*)(sm + SM_STG);
        float* sxs = (float*)(sm + SM_SXS);
        float* inv = (float*)(sm + SM_INV);
#pragma unroll
        for (int rr = 0; rr < 4; rr++) {
            int tl = wrp * 4 + rr;
            float4 v = *(const float4*)(x + (size_t)(t0 + tl) * EDIM + h * KD + l * 4);
            float mx = fmaxf(fmaxf(fabsf(v.x), fabsf(v.y)), fmaxf(fabsf(v.z), fabsf(v.w)));
#pragma unroll
            for (int off = 16; off; off >>= 1)
                mx = fmaxf(mx, __shfl_xor_sync(0xffffffffu, mx, off));
            if (l == 0) {
                sxs[tl] = mx * (1.f / 127.f);
                inv[tl] = (mx > 0.f) ? 127.f / mx : 0.f;
            }
            *(float4*)&stg[tl * 132 + l * 4] = v;
        }
    }
    __syncthreads();
    // ---- prologue pass 2: transpose -> dup-packed XS2 + int8 XQ ----
    {
        const float* stg = (const float*)(sm + SM_STG);
        u64* xs2 = (u64*)(sm + SM_XS2);
        int* xq  = (int*)(sm + SM_XQ);
        const int t = tid & 31;
        const float invv = ((const float*)(sm + SM_INV))[t];
#pragma unroll
        for (int r = 0; r < 4; r++) {
            int k4 = (tid >> 5) + 8 * r;
            float f0 = stg[t * 132 + 4*k4 + 0];
            float f1 = stg[t * 132 + 4*k4 + 1];
            float f2 = stg[t * 132 + 4*k4 + 2];
            float f3 = stg[t * 132 + 4*k4 + 3];
            xs2[(4*k4+0) * 32 + t] = pack2(f0, f0);
            xs2[(4*k4+1) * 32 + t] = pack2(f1, f1);
            xs2[(4*k4+2) * 32 + t] = pack2(f2, f2);
            xs2[(4*k4+3) * 32 + t] = pack2(f3, f3);
            int a0 = q8(f0, invv), a1 = q8(f1, invv), a2 = q8(f2, invv), a3 = q8(f3, invv);
            xq[k4 * 32 + t] = (a0 & 255) | ((a1 & 255) << 8) | ((a2 & 255) << 16) | ((a3 & 255) << 24);
        }
    }

    float fv[2]; int fi[2];
    float v1[2], v2[2], v3[2]; int i1[2], i2[2];
#pragma unroll
    for (int p = 0; p < 2; p++) {
        fv[p] = NEG_INF; fi[p] = 0;
        v1[p] = v2[p] = v3[p] = NEG_INF; i1[p] = OF; i2[p] = OF;
    }

#pragma unroll 1
    for (int it = 0; it < NIT; it++) {
        __syncthreads();   // previous chunk consumed; on it=0 also guards STG->WF alias
        // WF: [k][48 pairs] u64 ; 3072 16B-vectors
#pragma unroll
        for (int r = 0; r < 12; r++) {
            int i = tid + 256 * r;
            int k = i / 24, v = i % 24;
            CP16(sb + SM_WF + k * 384 + v * 16,
                 wtsrc + (size_t)k * OD + it * CWF + v * 4);
        }
        // WQ: [k4][32] int ; 256 vectors
        {
            int k4 = tid >> 3, s = tid & 7;
            CP16(sb + SM_WQ + k4 * 128 + s * 16,
                 wqsrc + (size_t)k4 * OI + it * CWQ + s * 4);
        }
        if (tid < 8)
            CP16(sb + SM_SWS + tid * 16, swsrc + it * CWQ + tid * 4);
        CPCOMMIT(); CPWAIT0();
        __syncthreads();

        u64 facc[2][3];
        int iacc[2][2];
#pragma unroll
        for (int p = 0; p < 2; p++) {
            facc[p][0] = facc[p][1] = facc[p][2] = 0ULL;
            iacc[p][0] = iacc[p][1] = 0;
        }

#pragma unroll 4
        for (int k4 = 0; k4 < NK4; k4++) {
            int2 xqv = *(const int2*)(sm + SM_XQ + (k4 * 32 + ty * 2) * 4);
            int2 wqv = *(const int2*)(sm + SM_WQ + (k4 * 32 + tx * 2) * 4);
            iacc[0][0] = __dp4a(xqv.x, wqv.x, iacc[0][0]);
            iacc[0][1] = __dp4a(xqv.x, wqv.y, iacc[0][1]);
            iacc[1][0] = __dp4a(xqv.y, wqv.x, iacc[1][0]);
            iacc[1][1] = __dp4a(xqv.y, wqv.y, iacc[1][1]);
#pragma unroll
            for (int j = 0; j < 4; j++) {
                const int k = k4 * 4 + j;
                ulonglong2 xa = *(const ulonglong2*)(sm + SM_XS2 + (k * 32 + ty * 2) * 8);
                u64 w0 = *(const u64*)(sm + SM_WF + (k * 48 + tx) * 8);
                u64 w1 = *(const u64*)(sm + SM_WF + (k * 48 + tx + 16) * 8);
                u64 w2 = *(const u64*)(sm + SM_WF + (k * 48 + tx + 32) * 8);
                facc[0][0] = ffma2(xa.x, w0, facc[0][0]);
                facc[0][1] = ffma2(xa.x, w1, facc[0][1]);
                facc[0][2] = ffma2(xa.x, w2, facc[0][2]);
                facc[1][0] = ffma2(xa.y, w0, facc[1][0]);
                facc[1][1] = ffma2(xa.y, w1, facc[1][1]);
                facc[1][2] = ffma2(xa.y, w2, facc[1][2]);
            }
        }

        // fold fp32 (exact top-1; ascending option order per thread)
#pragma unroll
        for (int p = 0; p < 2; p++) {
#pragma unroll
            for (int j = 0; j < 3; j++) {
                const int o = it * CWF + (tx + 16 * j) * 2;
                float q0, q1; unpack2(facc[p][j], q0, q1);
                if (q0 > fv[p]) { fv[p] = q0; fi[p] = o; }
                if (q1 > fv[p]) { fv[p] = q1; fi[p] = o + 1; }
            }
        }
        // fold int8 (top-3)
        {
            float2 s2 = *(const float2*)(sm + SM_SWS + tx * 8);
            const int ob = OF + it * CWQ + tx * 2;
#pragma unroll
            for (int p = 0; p < 2; p++) {
#pragma unroll
                for (int u = 0; u < 2; u++) {
                    float v = (float)iacc[p][u] * (u ? s2.y : s2.x);
                    int o = ob + u;
                    if (v > v1[p]) { v3[p] = v2[p]; v2[p] = v1[p]; i2[p] = i1[p]; v1[p] = v; i1[p] = o; }
                    else if (v > v2[p]) { v3[p] = v2[p]; v2[p] = v; i2[p] = o; }
                    else if (v > v3[p]) { v3[p] = v; }
                }
            }
        }
    }

    // ---- reduce across 16 tx lanes, decide / flag ----
#pragma unroll
    for (int p = 0; p < 2; p++) {
        float a1 = v1[p], a2 = v2[p], a3 = v3[p]; int j1 = i1[p], j2 = i2[p];
        float af = fv[p]; int jf = fi[p];
#pragma unroll
        for (int off = 1; off <= 8; off <<= 1) {
            float b1 = __shfl_xor_sync(0xffffffffu, a1, off);
            float b2 = __shfl_xor_sync(0xffffffffu, a2, off);
            float b3 = __shfl_xor_sync(0xffffffffu, a3, off);
            int   k1 = __shfl_xor_sync(0xffffffffu, j1, off);
            int   k2 = __shfl_xor_sync(0xffffffffu, j2, off);
            merge3(a1, a2, a3, j1, j2, b1, b2, b3, k1, k2);
            float bf = __shfl_xor_sync(0xffffffffu, af, off);
            int   kf = __shfl_xor_sync(0xffffffffu, jf, off);
            if (bf > af || (bf == af && kf < jf)) { af = bf; jf = kf; }
        }
        if (tx == 0) {
            const int t = t0 + ty * 2 + p;
            const int pair = t * NHEADS + h;
            const float sx = ((const float*)(sm + SM_SXS))[ty * 2 + p];
            float q1 = a1 * sx, q2 = a2 * sx, q3 = a3 * sx;
            const float M = fmaxf(af, q1);
            int idx = jf;
            if (q1 <= af - TH) {
                // fp32 winner certain
            } else if (q3 >= M - TH) {
                unsigned q = atomicAdd(&g_r2n[h], 1u);
                if (q < R2CAP) { g_r2[h][q] = t; g_best[pair] = 0ULL; }
            } else if (af <= q1 - TH && q2 < M - TH) {
                idx = j1;
            } else {
                unsigned has2 = (q2 >= M - TH) ? 1u : 0u;
                unsigned qq = atomicAdd(&g_r1n, 1u);
                g_r1[qq] = make_uint2((unsigned)pair,
                                      (unsigned)jf | ((unsigned)j1 << 10) |
                                      ((unsigned)j2 << 20) | (has2 << 30));
            }
            g_idx[pair] = idx;
        }
    }
}

// ---------------- tier-1 rescue ----------------
__global__ __launch_bounds__(256) void rescue1_kernel(const float* __restrict__ x,
                                                      const float* __restrict__ w) {
    const unsigned cnt = g_r1n;
    const int l = threadIdx.x & 31;
    const int gw = (blockIdx.x * 256 + threadIdx.x) >> 5;
    for (unsigned e = gw; e < cnt; e += 2048) {
        uint2 ent = g_r1[e];
        int pair = (int)ent.x, t = pair >> 4, h = pair & 15;
        int c0 = (int)(ent.y & 0x3FF);
        int c1 = (int)((ent.y >> 10) & 0x3FF);
        int c2 = (int)((ent.y >> 20) & 0x3FF);
        bool has2 = (ent.y >> 30) != 0;
        float4 xv = ((const float4*)(x + (size_t)t * EDIM + h * KD))[l];
        float4 w0 = ((const float4*)(w + ((size_t)h * OD + c0) * KD))[l];
        float4 w1 = ((const float4*)(w + ((size_t)h * OD + c1) * KD))[l];
        float4 w2 = ((const float4*)(w + ((size_t)h * OD + c2) * KD))[l];
        float d0 = xv.x * w0.x + xv.y * w0.y + xv.z * w0.z + xv.w * w0.w;
        float d1 = xv.x * w1.x + xv.y * w1.y + xv.z * w1.z + xv.w * w1.w;
        float d2 = xv.x * w2.x + xv.y * w2.y + xv.z * w2.z + xv.w * w2.w;
#pragma unroll
        for (int off = 16; off; off >>= 1) {
            d0 += __shfl_xor_sync(0xffffffffu, d0, off);
            d1 += __shfl_xor_sync(0xffffffffu, d1, off);
            d2 += __shfl_xor_sync(0xffffffffu, d2, off);
        }
        if (l == 0) {
            float bd = d0; int bi = c0;
            if (d1 > bd || (d1 == bd && c1 < bi)) { bd = d1; bi = c1; }
            if (has2 && (d2 > bd || (d2 == bd && c2 < bi))) { bd = d2; bi = c2; }
            g_idx[pair] = bi;
        }
    }
}

// ---------------- tier-2 rescue (exact full recompute, coalesced w from g_wt) ----------------
__global__ __launch_bounds__(256) void rescue2_kernel(const float* __restrict__ x) {
    __shared__ __align__(16) float xs[128][36];
    __shared__ int toks[32];
    const int h = blockIdx.x, c = blockIdx.y, slab = blockIdx.z;
    unsigned n = g_r2n[h]; if (n > R2CAP) n = R2CAP;
    const int e0 = slab * 32;
    if (e0 >= (int)n) return;
    const int cnt = ((int)n - e0 < 32) ? ((int)n - e0) : 32;
    const int tid = threadIdx.x;

    if (tid < cnt) toks[tid] = g_r2[h][e0 + tid];
    __syncthreads();
    for (int i = tid; i < cnt * 32; i += 256) {
        int e = i >> 5, k4 = i & 31;
        float4 v = ((const float4*)(x + (size_t)toks[e] * EDIM + h * KD))[k4];
        xs[k4*4+0][e] = v.x; xs[k4*4+1][e] = v.y;
        xs[k4*4+2][e] = v.z; xs[k4*4+3][e] = v.w;
    }
    __syncthreads();

    const int ol = tid & 127, tg = tid >> 7;
    const int o = c * 128 + ol;
    const float* wcol = g_wt + (size_t)h * KD * OD + o;

    float acc[16];
#pragma unroll
    for (int u = 0; u < 16; u++) acc[u] = 0.f;

#pragma unroll 4
    for (int k = 0; k < KD; k++) {
        float wv = wcol[(size_t)k * OD];
        float4 x0 = *(const float4*)&xs[k][tg * 16];
        float4 x1 = *(const float4*)&xs[k][tg * 16 + 4];
        float4 x2 = *(const float4*)&xs[k][tg * 16 + 8];
        float4 x3 = *(const float4*)&xs[k][tg * 16 + 12];
        acc[0]  += wv * x0.x; acc[1]  += wv * x0.y; acc[2]  += wv * x0.z; acc[3]  += wv * x0.w;
        acc[4]  += wv * x1.x; acc[5]  += wv * x1.y; acc[6]  += wv * x1.z; acc[7]  += wv * x1.w;
        acc[8]  += wv * x2.x; acc[9]  += wv * x2.y; acc[10] += wv * x2.z; acc[11] += wv * x2.w;
        acc[12] += wv * x3.x; acc[13] += wv * x3.y; acc[14] += wv * x3.z; acc[15] += wv * x3.w;
    }

#pragma unroll
    for (int u = 0; u < 16; u++) {
        float v = acc[u]; int oo = o;
#pragma unroll
        for (int off = 16; off; off >>= 1) {
            float v2 = __shfl_xor_sync(0xffffffffu, v, off);
            int   o2 = __shfl_xor_sync(0xffffffffu, oo, off);
            if (v2 > v || (v2 == v && o2 < oo)) { v = v2; oo = o2; }
        }
        int te = tg * 16 + u;
        if ((tid & 31) == 0 && te < cnt) {
            u64 key = ((u64)enc_f(v) << 32) | (unsigned)(OD - 1 - oo);
            atomicMax(&g_best[toks[te] * NHEADS + h], key);
        }
    }
}

__global__ void decode_kernel() {
    const int h = blockIdx.x;
    unsigned n = g_r2n[h]; if (n > R2CAP) n = R2CAP;
    for (unsigned e = threadIdx.x; e < n; e += blockDim.x) {
        int pair = g_r2[h][e] * NHEADS + h;
        u64 key = g_best[pair];
        g_idx[pair] = (OD - 1) - (int)(key & 0xFFFFFFFFULL);
    }
}

// ---------------- gather ----------------
__global__ __launch_bounds__(256) void gather_kernel(const float* __restrict__ cb,
                                                     float* __restrict__ out) {
    const float4* cb4 = (const float4*)cb;
    float4* out4 = (float4*)out;
    int q = blockIdx.x * blockDim.x + threadIdx.x;
    int t = q >> 9, r = q & 511;
    int h = r >> 5, j = r & 31;
    int bi = g_idx[t * NHEADS + h];
    out4[(size_t)t * (EDIM / 4) + h * (KD / 4) + j] =
        cb4[((size_t)h * OD + bi) * (KD / 4) + j];
}

extern "C" void kernel_launch(void* const* d_in, const int* in_sizes, int n_in,
                              void* d_out, int out_size) {
    const float* x  = (const float*)d_in[0];
    const float* w  = (const float*)d_in[1];
    const float* cb = (const float*)d_in[2];
    // d_in[3] temperature: mathematically irrelevant in the forward pass.
    float* out = (float*)d_out;

    cudaFuncSetAttribute(vq_hybrid_kernel,
                         cudaFuncAttributeMaxDynamicSharedMemorySize, SM_TOT);

    prep_w_kernel<<<dim3(OD / 32, NHEADS), 256>>>(w);
    vq_hybrid_kernel<<<dim3(NTOK / TM, NHEADS), 256, SM_TOT>>>(x);
    rescue1_kernel<<<256, 256>>>(x, w);
    rescue2_kernel<<<dim3(NHEADS, 8, R2CAP / 32), 256>>>(x);
    decode_kernel<<<NHEADS, 256>>>();
    gather_kernel<<<(NTOK * EDIM / 4) / 256, 256>>>(cb, out);
}

// round 12
// speedup vs baseline: 1.2033x; 1.2033x over previous
#include <cuda_runtime.h>
#include <cstdint>

#define NHEADS 16
#define OD     1024
#define OF     768        // fp32-exact options [0,768)
#define OI     256        // int8 options [768,1024)
#define KD     128
#define NK4    32
#define NTOK   4096
#define EDIM   2048
#define TM     128        // tokens per main block
#define NTHR   512
#define CWF    96         // fp32 options per iter
#define CWQ    32         // int8 options per iter
#define NIT    8
#define TH     0.032f
#define NEG_INF (-3.402823466e38f)
#define R2CAP  1024

typedef unsigned long long u64;

// ---------------- device scratch ----------------
__device__ __align__(16) float g_wt[(size_t)NHEADS*KD*OD];   // [h][k][o] fp32 transposed (ALL)
__device__ __align__(16) int   g_wq[(size_t)NHEADS*NK4*OI];  // [h][k4][o-768] packed int8
__device__ __align__(16) float g_sw[NHEADS*OI];
__device__ int      g_idx[NTOK*NHEADS];
__device__ unsigned g_r1n;
__device__ uint2    g_r1[NTOK*NHEADS];
__device__ unsigned g_r2n[NHEADS];
__device__ int      g_r2[NHEADS][R2CAP];
__device__ u64      g_best[NTOK*NHEADS];

// ---------------- main-kernel smem (bytes) ----------------
// Staging aliases WF; stages 64 tokens per half-pass:
// 64 * 132 * 4 = 33792 bytes <= 49152 (WF region) -> never touches WQ/XQ.
// Stride 132 floats = 528 bytes, 16B-aligned rows (float4-safe).
#define SM_XS2 0                        // u64 [128 k][128 tok] x dup   (131072)
#define SM_WF  131072                   // u64 [128 k][48 pairs]        (49152)
#define SM_STG SM_WF                    // f32 [64 tok][132] staging (alias, prologue only)
#define SM_WQ  180224                   // int [32 k4][32 opt]          (4096)
#define SM_XQ  184320                   // int [32 k4][128 tok]         (16384)
#define SM_SWS 200704                   // 32 f32
#define SM_SXS 200832                   // 128 f32
#define SM_INV 201344                   // 128 f32
#define SM_TOT 201856

// ---------------- helpers ----------------
#define CP16(dst, src) \
    asm volatile("cp.async.cg.shared.global [%0], [%1], 16;" :: "r"(dst), "l"(src))
#define CPCOMMIT() asm volatile("cp.async.commit_group;" ::: "memory")
#define CPWAIT0()  asm volatile("cp.async.wait_group 0;" ::: "memory")

__device__ __forceinline__ uint32_t smem_u32(const void* p) {
    uint32_t a;
    asm("{ .reg .u64 t; cvta.to.shared.u64 t, %1; cvt.u32.u64 %0, t; }" : "=r"(a) : "l"(p));
    return a;
}
__device__ __forceinline__ u64 pack2(float lo, float hi) {
    u64 r; asm("mov.b64 %0, {%1, %2};" : "=l"(r) : "f"(lo), "f"(hi)); return r;
}
__device__ __forceinline__ void unpack2(u64 v, float &lo, float &hi) {
    asm("mov.b64 {%0, %1}, %2;" : "=f"(lo), "=f"(hi) : "l"(v));
}
__device__ __forceinline__ u64 ffma2(u64 a, u64 b, u64 c) {
    u64 d; asm("fma.rn.f32x2 %0, %1, %2, %3;" : "=l"(d) : "l"(a), "l"(b), "l"(c));
    return d;
}
__device__ __forceinline__ int q8(float v, float inv) {
    int a = __float2int_rn(v * inv);
    return a < -127 ? -127 : (a > 127 ? 127 : a);
}
__device__ __forceinline__ void merge3(float& a1, float& a2, float& a3, int& j1, int& j2,
                                       float b1, float b2, float b3, int k1, int k2) {
    if (b1 > a1 || (b1 == a1 && k1 < j1)) {
        float t1 = a1, t2 = a2, t3 = a3; int u1 = j1, u2 = j2;
        a1 = b1; a2 = b2; a3 = b3; j1 = k1; j2 = k2;
        b1 = t1; b2 = t2; b3 = t3; k1 = u1; k2 = u2;
    }
    if (b1 > a2 || (b1 == a2 && k1 < j2)) { a3 = fmaxf(a2, b2); a2 = b1; j2 = k1; }
    else                                  { a3 = fmaxf(a3, b1); }
}
__device__ __forceinline__ unsigned enc_f(float f) {
    unsigned u = __float_as_uint(f);
    return (u & 0x80000000u) ? ~u : (u | 0x80000000u);
}

// ---------------- w preprocessing ----------------
__global__ __launch_bounds__(256) void prep_w_kernel(const float* __restrict__ w) {
    __shared__ float trf[128 * 33];
    __shared__ float sws_s[32], invs[32];
    if (blockIdx.x == 0 && blockIdx.y == 0) {
        if (threadIdx.x == 0) g_r1n = 0;
        if (threadIdx.x < NHEADS) g_r2n[threadIdx.x] = 0;
    }
    const int h = blockIdx.y, o0 = blockIdx.x * 32;
    const int tid = threadIdx.x, l = tid & 31, wid = tid >> 5;

    for (int r = wid; r < 32; r += 8) {
        float4 v = *(const float4*)(w + ((size_t)h * OD + o0 + r) * KD + l * 4);
        trf[(4*l+0)*33 + r] = v.x; trf[(4*l+1)*33 + r] = v.y;
        trf[(4*l+2)*33 + r] = v.z; trf[(4*l+3)*33 + r] = v.w;
        if (o0 >= OF) {
            float mx = fmaxf(fmaxf(fabsf(v.x), fabsf(v.y)), fmaxf(fabsf(v.z), fabsf(v.w)));
#pragma unroll
            for (int off = 16; off; off >>= 1)
                mx = fmaxf(mx, __shfl_xor_sync(0xffffffffu, mx, off));
            if (l == 0) {
                sws_s[r] = mx * (1.f / 127.f);
                invs[r]  = (mx > 0.f) ? 127.f / mx : 0.f;
            }
        }
    }
    __syncthreads();
    for (int i = tid; i < 4096; i += 256) {
        int k = i >> 5, rl = i & 31;
        g_wt[((size_t)h * KD + k) * OD + o0 + rl] = trf[k * 33 + rl];
    }
    if (o0 >= OF) {
        for (int i = tid; i < 1024; i += 256) {
            int k4 = i >> 5, rl = i & 31;
            float inv = invs[rl];
            int a0 = q8(trf[(4*k4+0)*33 + rl], inv);
            int a1 = q8(trf[(4*k4+1)*33 + rl], inv);
            int a2 = q8(trf[(4*k4+2)*33 + rl], inv);
            int a3 = q8(trf[(4*k4+3)*33 + rl], inv);
            g_wq[((size_t)h * NK4 + k4) * OI + (o0 - OF) + rl] =
                (a0 & 255) | ((a1 & 255) << 8) | ((a2 & 255) << 16) | ((a3 & 255) << 24);
        }
        if (tid < 32) g_sw[h * OI + (o0 - OF) + tid] = sws_s[tid];
    }
}

// ---------------- main hybrid kernel: 128 tok x 1 head, 512 threads ----------------
// 16 tx x 32 ty; thread tile = 4 tokens x (6 fp32 + 2 int8) options
__global__ __launch_bounds__(NTHR, 1) void vq_hybrid_kernel(const float* __restrict__ x) {
    extern __shared__ char sm[];
    const uint32_t sb = smem_u32(sm);
    const int tid = threadIdx.x, l = tid & 31, wrp = tid >> 5;
    const int tx = tid & 15, ty = tid >> 4;
    const int t0 = blockIdx.x * TM, h = blockIdx.y;

    const float* wtsrc = g_wt + (size_t)h * KD * OD;
    const int*   wqsrc = g_wq + (size_t)h * NK4 * OI;
    const float* swsrc = g_sw + (size_t)h * OI;

    // ---- prologue: two half-passes of 64 tokens (staging inside WF region) ----
    {
        float* stg = (float*)(sm + SM_STG);        // [64][132], 16B-aligned rows
        float* sxs = (float*)(sm + SM_SXS);
        float* inv = (float*)(sm + SM_INV);
        u64*   xs2 = (u64*)(sm + SM_XS2);
        int*   xq  = (int*)(sm + SM_XQ);
#pragma unroll 1
        for (int half = 0; half < 2; half++) {
            const int tb = half * 64;
            // pass 1: load 64 rows (each warp: 4 tokens), row-max, stage row-major
#pragma unroll
            for (int rr = 0; rr < 4; rr++) {
                int tl = wrp * 4 + rr;             // 0..63
                float4 v = *(const float4*)(x + (size_t)(t0 + tb + tl) * EDIM + h * KD + l * 4);
                float mx = fmaxf(fmaxf(fabsf(v.x), fabsf(v.y)), fmaxf(fabsf(v.z), fabsf(v.w)));
#pragma unroll
                for (int off = 16; off; off >>= 1)
                    mx = fmaxf(mx, __shfl_xor_sync(0xffffffffu, mx, off));
                if (l == 0) {
                    sxs[tb + tl] = mx * (1.f / 127.f);
                    inv[tb + tl] = (mx > 0.f) ? 127.f / mx : 0.f;
                }
                *(float4*)&stg[tl * 132 + l * 4] = v;
            }
            __syncthreads();
            // pass 2: transpose 64 tokens -> dup-packed XS2 + int8 XQ
            {
                const int t = tid & 63;            // local token
                const float invv = inv[tb + t];
#pragma unroll
                for (int r = 0; r < 4; r++) {
                    int k4 = (tid >> 6) + 8 * r;   // 0..31
                    float4 f = *(const float4*)&stg[t * 132 + 4 * k4];
                    xs2[(4*k4+0) * TM + tb + t] = pack2(f.x, f.x);
                    xs2[(4*k4+1) * TM + tb + t] = pack2(f.y, f.y);
                    xs2[(4*k4+2) * TM + tb + t] = pack2(f.z, f.z);
                    xs2[(4*k4+3) * TM + tb + t] = pack2(f.w, f.w);
                    int a0 = q8(f.x, invv), a1 = q8(f.y, invv);
                    int a2 = q8(f.z, invv), a3 = q8(f.w, invv);
                    xq[k4 * TM + tb + t] =
                        (a0 & 255) | ((a1 & 255) << 8) | ((a2 & 255) << 16) | ((a3 & 255) << 24);
                }
            }
            __syncthreads();
        }
    }

    float fv[4]; int fi[4];
    float v1[4], v2[4], v3[4]; int i1[4], i2[4];
#pragma unroll
    for (int p = 0; p < 4; p++) {
        fv[p] = NEG_INF; fi[p] = 0;
        v1[p] = v2[p] = v3[p] = NEG_INF; i1[p] = OF; i2[p] = OF;
    }

#pragma unroll 1
    for (int it = 0; it < NIT; it++) {
        __syncthreads();   // previous chunk consumed; on it=0 guards STG->WF alias
        // WF: [k][48 pairs] u64 = 3072 16B-vectors
#pragma unroll
        for (int r = 0; r < 6; r++) {
            int i = tid + NTHR * r;
            int k = i / 24, v = i % 24;
            CP16(sb + SM_WF + k * 384 + v * 16,
                 wtsrc + (size_t)k * OD + it * CWF + v * 4);
        }
        // WQ: [k4][32] = 256 vectors
        if (tid < 256) {
            int k4 = tid >> 3, s = tid & 7;
            CP16(sb + SM_WQ + k4 * 128 + s * 16,
                 wqsrc + (size_t)k4 * OI + it * CWQ + s * 4);
        }
        if (tid < 8)
            CP16(sb + SM_SWS + tid * 16, swsrc + it * CWQ + tid * 4);
        CPCOMMIT(); CPWAIT0();
        __syncthreads();

        u64 facc[4][3];
        int iacc[4][2];
#pragma unroll
        for (int p = 0; p < 4; p++) {
            facc[p][0] = facc[p][1] = facc[p][2] = 0ULL;
            iacc[p][0] = iacc[p][1] = 0;
        }

#pragma unroll 2
        for (int k4 = 0; k4 < NK4; k4++) {
            int4 xqv = *(const int4*)(sm + SM_XQ + (k4 * TM + ty * 4) * 4);
            int2 wqv = *(const int2*)(sm + SM_WQ + (k4 * 32 + tx * 2) * 4);
            iacc[0][0] = __dp4a(xqv.x, wqv.x, iacc[0][0]);
            iacc[0][1] = __dp4a(xqv.x, wqv.y, iacc[0][1]);
            iacc[1][0] = __dp4a(xqv.y, wqv.x, iacc[1][0]);
            iacc[1][1] = __dp4a(xqv.y, wqv.y, iacc[1][1]);
            iacc[2][0] = __dp4a(xqv.z, wqv.x, iacc[2][0]);
            iacc[2][1] = __dp4a(xqv.z, wqv.y, iacc[2][1]);
            iacc[3][0] = __dp4a(xqv.w, wqv.x, iacc[3][0]);
            iacc[3][1] = __dp4a(xqv.w, wqv.y, iacc[3][1]);
#pragma unroll
            for (int j = 0; j < 4; j++) {
                const int k = k4 * 4 + j;
                ulonglong2 xa = *(const ulonglong2*)(sm + SM_XS2 + (k * TM + ty * 4) * 8);
                ulonglong2 xb = *(const ulonglong2*)(sm + SM_XS2 + (k * TM + ty * 4 + 2) * 8);
                u64 w0 = *(const u64*)(sm + SM_WF + (k * 48 + tx) * 8);
                u64 w1 = *(const u64*)(sm + SM_WF + (k * 48 + tx + 16) * 8);
                u64 w2 = *(const u64*)(sm + SM_WF + (k * 48 + tx + 32) * 8);
                facc[0][0] = ffma2(xa.x, w0, facc[0][0]);
                facc[0][1] = ffma2(xa.x, w1, facc[0][1]);
                facc[0][2] = ffma2(xa.x, w2, facc[0][2]);
                facc[1][0] = ffma2(xa.y, w0, facc[1][0]);
                facc[1][1] = ffma2(xa.y, w1, facc[1][1]);
                facc[1][2] = ffma2(xa.y, w2, facc[1][2]);
                facc[2][0] = ffma2(xb.x, w0, facc[2][0]);
                facc[2][1] = ffma2(xb.x, w1, facc[2][1]);
                facc[2][2] = ffma2(xb.x, w2, facc[2][2]);
                facc[3][0] = ffma2(xb.y, w0, facc[3][0]);
                facc[3][1] = ffma2(xb.y, w1, facc[3][1]);
                facc[3][2] = ffma2(xb.y, w2, facc[3][2]);
            }
        }

        // fold fp32 (exact top-1)
#pragma unroll
        for (int p = 0; p < 4; p++) {
#pragma unroll
            for (int j = 0; j < 3; j++) {
                const int o = it * CWF + (tx + 16 * j) * 2;
                float q0, q1; unpack2(facc[p][j], q0, q1);
                if (q0 > fv[p]) { fv[p] = q0; fi[p] = o; }
                if (q1 > fv[p]) { fv[p] = q1; fi[p] = o + 1; }
            }
        }
        // fold int8 (top-3)
        {
            float2 s2 = *(const float2*)(sm + SM_SWS + tx * 8);
            const int ob = OF + it * CWQ + tx * 2;
#pragma unroll
            for (int p = 0; p < 4; p++) {
#pragma unroll
                for (int u = 0; u < 2; u++) {
                    float v = (float)iacc[p][u] * (u ? s2.y : s2.x);
                    int o = ob + u;
                    if (v > v1[p]) { v3[p] = v2[p]; v2[p] = v1[p]; i2[p] = i1[p]; v1[p] = v; i1[p] = o; }
                    else if (v > v2[p]) { v3[p] = v2[p]; v2[p] = v; i2[p] = o; }
                    else if (v > v3[p]) { v3[p] = v; }
                }
            }
        }
    }

    // ---- reduce across 16 tx lanes, decide / flag ----
#pragma unroll
    for (int p = 0; p < 4; p++) {
        float a1 = v1[p], a2 = v2[p], a3 = v3[p]; int j1 = i1[p], j2 = i2[p];
        float af = fv[p]; int jf = fi[p];
#pragma unroll
        for (int off = 1; off <= 8; off <<= 1) {
            float b1 = __shfl_xor_sync(0xffffffffu, a1, off);
            float b2 = __shfl_xor_sync(0xffffffffu, a2, off);
            float b3 = __shfl_xor_sync(0xffffffffu, a3, off);
            int   k1 = __shfl_xor_sync(0xffffffffu, j1, off);
            int   k2 = __shfl_xor_sync(0xffffffffu, j2, off);
            merge3(a1, a2, a3, j1, j2, b1, b2, b3, k1, k2);
            float bf = __shfl_xor_sync(0xffffffffu, af, off);
            int   kf = __shfl_xor_sync(0xffffffffu, jf, off);
            if (bf > af || (bf == af && kf < jf)) { af = bf; jf = kf; }
        }
        if (tx == 0) {
            const int t = t0 + ty * 4 + p;
            const int pair = t * NHEADS + h;
            const float sx = ((const float*)(sm + SM_SXS))[ty * 4 + p];
            float q1 = a1 * sx, q2 = a2 * sx, q3 = a3 * sx;
            const float M = fmaxf(af, q1);
            int idx = jf;
            if (q1 <= af - TH) {
                // fp32 winner certain
            } else if (q3 >= M - TH) {
                unsigned q = atomicAdd(&g_r2n[h], 1u);
                if (q < R2CAP) { g_r2[h][q] = t; g_best[pair] = 0ULL; }
            } else if (af <= q1 - TH && q2 < M - TH) {
                idx = j1;
            } else {
                unsigned has2 = (q2 >= M - TH) ? 1u : 0u;
                unsigned qq = atomicAdd(&g_r1n, 1u);
                g_r1[qq] = make_uint2((unsigned)pair,
                                      (unsigned)jf | ((unsigned)j1 << 10) |
                                      ((unsigned)j2 << 20) | (has2 << 30));
            }
            g_idx[pair] = idx;
        }
    }
}

// ---------------- tier-1 rescue ----------------
__global__ __launch_bounds__(256) void rescue1_kernel(const float* __restrict__ x,
                                                      const float* __restrict__ w) {
    const unsigned cnt = g_r1n;
    const int l = threadIdx.x & 31;
    const int gw = (blockIdx.x * 256 + threadIdx.x) >> 5;
    for (unsigned e = gw; e < cnt; e += 2048) {
        uint2 ent = g_r1[e];
        int pair = (int)ent.x, t = pair >> 4, h = pair & 15;
        int c0 = (int)(ent.y & 0x3FF);
        int c1 = (int)((ent.y >> 10) & 0x3FF);
        int c2 = (int)((ent.y >> 20) & 0x3FF);
        bool has2 = (ent.y >> 30) != 0;
        float4 xv = ((const float4*)(x + (size_t)t * EDIM + h * KD))[l];
        float4 w0 = ((const float4*)(w + ((size_t)h * OD + c0) * KD))[l];
        float4 w1 = ((const float4*)(w + ((size_t)h * OD + c1) * KD))[l];
        float4 w2 = ((const float4*)(w + ((size_t)h * OD + c2) * KD))[l];
        float d0 = xv.x * w0.x + xv.y * w0.y + xv.z * w0.z + xv.w * w0.w;
        float d1 = xv.x * w1.x + xv.y * w1.y + xv.z * w1.z + xv.w * w1.w;
        float d2 = xv.x * w2.x + xv.y * w2.y + xv.z * w2.z + xv.w * w2.w;
#pragma unroll
        for (int off = 16; off; off >>= 1) {
            d0 += __shfl_xor_sync(0xffffffffu, d0, off);
            d1 += __shfl_xor_sync(0xffffffffu, d1, off);
            d2 += __shfl_xor_sync(0xffffffffu, d2, off);
        }
        if (l == 0) {
            float bd = d0; int bi = c0;
            if (d1 > bd || (d1 == bd && c1 < bi)) { bd = d1; bi = c1; }
            if (has2 && (d2 > bd || (d2 == bd && c2 < bi))) { bd = d2; bi = c2; }
            g_idx[pair] = bi;
        }
    }
}

// ---------------- tier-2 rescue (exact full recompute, coalesced w from g_wt) ----------------
__global__ __launch_bounds__(256) void rescue2_kernel(const float* __restrict__ x) {
    __shared__ __align__(16) float xs[128][36];
    __shared__ int toks[32];
    const int h = blockIdx.x, c = blockIdx.y, slab = blockIdx.z;
    unsigned n = g_r2n[h]; if (n > R2CAP) n = R2CAP;
    const int e0 = slab * 32;
    if (e0 >= (int)n) return;
    const int cnt = ((int)n - e0 < 32) ? ((int)n - e0) : 32;
    const int tid = threadIdx.x;

    if (tid < cnt) toks[tid] = g_r2[h][e0 + tid];
    __syncthreads();
    for (int i = tid; i < cnt * 32; i += 256) {
        int e = i >> 5, k4 = i & 31;
        float4 v = ((const float4*)(x + (size_t)toks[e] * EDIM + h * KD))[k4];
        xs[k4*4+0][e] = v.x; xs[k4*4+1][e] = v.y;
        xs[k4*4+2][e] = v.z; xs[k4*4+3][e] = v.w;
    }
    __syncthreads();

    const int ol = tid & 127, tg = tid >> 7;
    const int o = c * 128 + ol;
    const float* wcol = g_wt + (size_t)h * KD * OD + o;

    float acc[16];
#pragma unroll
    for (int u = 0; u < 16; u++) acc[u] = 0.f;

#pragma unroll 4
    for (int k = 0; k < KD; k++) {
        float wv = wcol[(size_t)k * OD];
        float4 x0 = *(const float4*)&xs[k][tg * 16];
        float4 x1 = *(const float4*)&xs[k][tg * 16 + 4];
        float4 x2 = *(const float4*)&xs[k][tg * 16 + 8];
        float4 x3 = *(const float4*)&xs[k][tg * 16 + 12];
        acc[0]  += wv * x0.x; acc[1]  += wv * x0.y; acc[2]  += wv * x0.z; acc[3]  += wv * x0.w;
        acc[4]  += wv * x1.x; acc[5]  += wv * x1.y; acc[6]  += wv * x1.z; acc[7]  += wv * x1.w;
        acc[8]  += wv * x2.x; acc[9]  += wv * x2.y; acc[10] += wv * x2.z; acc[11] += wv * x2.w;
        acc[12] += wv * x3.x; acc[13] += wv * x3.y; acc[14] += wv * x3.z; acc[15] += wv * x3.w;
    }

#pragma unroll
    for (int u = 0; u < 16; u++) {
        float v = acc[u]; int oo = o;
#pragma unroll
        for (int off = 16; off; off >>= 1) {
            float v2 = __shfl_xor_sync(0xffffffffu, v, off);
            int   o2 = __shfl_xor_sync(0xffffffffu, oo, off);
            if (v2 > v || (v2 == v && o2 < oo)) { v = v2; oo = o2; }
        }
        int te = tg * 16 + u;
        if ((tid & 31) == 0 && te < cnt) {
            u64 key = ((u64)enc_f(v) << 32) | (unsigned)(OD - 1 - oo);
            atomicMax(&g_best[toks[te] * NHEADS + h], key);
        }
    }
}

__global__ void decode_kernel() {
    const int h = blockIdx.x;
    unsigned n = g_r2n[h]; if (n > R2CAP) n = R2CAP;
    for (unsigned e = threadIdx.x; e < n; e += blockDim.x) {
        int pair = g_r2[h][e] * NHEADS + h;
        u64 key = g_best[pair];
        g_idx[pair] = (OD - 1) - (int)(key & 0xFFFFFFFFULL);
    }
}

// ---------------- gather ----------------
__global__ __launch_bounds__(256) void gather_kernel(const float* __restrict__ cb,
                                                     float* __restrict__ out) {
    const float4* cb4 = (const float4*)cb;
    float4* out4 = (float4*)out;
    int q = blockIdx.x * blockDim.x + threadIdx.x;
    int t = q >> 9, r = q & 511;
    int h = r >> 5, j = r & 31;
    int bi = g_idx[t * NHEADS + h];
    out4[(size_t)t * (EDIM / 4) + h * (KD / 4) + j] =
        cb4[((size_t)h * OD + bi) * (KD / 4) + j];
}

extern "C" void kernel_launch(void* const* d_in, const int* in_sizes, int n_in,
                              void* d_out, int out_size) {
    const float* x  = (const float*)d_in[0];
    const float* w  = (const float*)d_in[1];
    const float* cb = (const float*)d_in[2];
    // d_in[3] temperature: mathematically irrelevant in the forward pass.
    float* out = (float*)d_out;

    cudaFuncSetAttribute(vq_hybrid_kernel,
                         cudaFuncAttributeMaxDynamicSharedMemorySize, SM_TOT);

    prep_w_kernel<<<dim3(OD / 32, NHEADS), 256>>>(w);
    vq_hybrid_kernel<<<dim3(NTOK / TM, NHEADS), NTHR, SM_TOT>>>(x);
    rescue1_kernel<<<256, 256>>>(x, w);
    rescue2_kernel<<<dim3(NHEADS, 8, R2CAP / 32), 256>>>(x);
    decode_kernel<<<NHEADS, 256>>>();
    gather_kernel<<<(NTOK * EDIM / 4) / 256, 256>>>(cb, out);
}

// round 13
// speedup vs baseline: 1.2360x; 1.0271x over previous
#include <cuda_runtime.h>
#include <cstdint>

#define NHEADS 16
#define OD     1024
#define OF     768        // fp32-exact options [0,768)
#define OI     256        // int8 options [768,1024)
#define KD     128
#define NK4    32
#define NTOK   4096
#define EDIM   2048
#define TM     64         // tokens per main block
#define NTHR   256
#define CWF    64         // fp32 options per iter
#define CWQ    32         // int8 options per iter (iters 0-7 only)
#define NIT    12
#define TH     0.032f
#define NEG_INF (-3.402823466e38f)
#define R2CAP  1024

typedef unsigned long long u64;

// ---------------- device scratch ----------------
__device__ __align__(16) float g_wt[(size_t)NHEADS*KD*OD];   // [h][k][o] fp32 transposed (ALL)
__device__ __align__(16) int   g_wq[(size_t)NHEADS*NK4*OI];  // [h][k4][o-768] packed int8
__device__ __align__(16) float g_sw[NHEADS*OI];
__device__ int      g_idx[NTOK*NHEADS];
__device__ unsigned g_r1n;
__device__ uint2    g_r1[NTOK*NHEADS];
__device__ unsigned g_r2n[NHEADS];
__device__ int      g_r2[NHEADS][R2CAP];
__device__ u64      g_best[NTOK*NHEADS];

// ---------------- main-kernel smem (bytes), occ 2 ----------------
// Staging [64][132] f32 = 33792B aliases WF (32768) + first 1KB of WQ.
// Safe: staging is consumed in prologue pass 2 (which writes only XS2/XQ,
// both outside the staged range); WF/WQ first written by iter-0 cp.async
// strictly after the prologue's closing __syncthreads().
#define SM_XS2 0                        // u64 [128 k][64 tok] x dup    (65536)
#define SM_WF  65536                    // u64 [128 k][32 pairs]        (32768)
#define SM_STG SM_WF                    // f32 [64 tok][132] staging (alias)
#define SM_WQ  98304                    // int [32 k4][32 opt]          (4096)
#define SM_XQ  102400                   // int [32 k4][64 tok]          (8192)
#define SM_SWS 110592                   // 32 f32
#define SM_SXS 110720                   // 64 f32
#define SM_INV 110976                   // 64 f32
#define SM_TOT 111232

// ---------------- helpers ----------------
#define CP16(dst, src) \
    asm volatile("cp.async.cg.shared.global [%0], [%1], 16;" :: "r"(dst), "l"(src))
#define CPCOMMIT() asm volatile("cp.async.commit_group;" ::: "memory")
#define CPWAIT0()  asm volatile("cp.async.wait_group 0;" ::: "memory")

__device__ __forceinline__ uint32_t smem_u32(const void* p) {
    uint32_t a;
    asm("{ .reg .u64 t; cvta.to.shared.u64 t, %1; cvt.u32.u64 %0, t; }" : "=r"(a) : "l"(p));
    return a;
}
__device__ __forceinline__ u64 pack2(float lo, float hi) {
    u64 r; asm("mov.b64 %0, {%1, %2};" : "=l"(r) : "f"(lo), "f"(hi)); return r;
}
__device__ __forceinline__ void unpack2(u64 v, float &lo, float &hi) {
    asm("mov.b64 {%0, %1}, %2;" : "=f"(lo), "=f"(hi) : "l"(v));
}
__device__ __forceinline__ u64 ffma2(u64 a, u64 b, u64 c) {
    u64 d; asm("fma.rn.f32x2 %0, %1, %2, %3;" : "=l"(d) : "l"(a), "l"(b), "l"(c));
    return d;
}
__device__ __forceinline__ int q8(float v, float inv) {
    int a = __float2int_rn(v * inv);
    return a < -127 ? -127 : (a > 127 ? 127 : a);
}
__device__ __forceinline__ void merge3(float& a1, float& a2, float& a3, int& j1, int& j2,
                                       float b1, float b2, float b3, int k1, int k2) {
    if (b1 > a1 || (b1 == a1 && k1 < j1)) {
        float t1 = a1, t2 = a2, t3 = a3; int u1 = j1, u2 = j2;
        a1 = b1; a2 = b2; a3 = b3; j1 = k1; j2 = k2;
        b1 = t1; b2 = t2; b3 = t3; k1 = u1; k2 = u2;
    }
    if (b1 > a2 || (b1 == a2 && k1 < j2)) { a3 = fmaxf(a2, b2); a2 = b1; j2 = k1; }
    else                                  { a3 = fmaxf(a3, b1); }
}
__device__ __forceinline__ unsigned enc_f(float f) {
    unsigned u = __float_as_uint(f);
    return (u & 0x80000000u) ? ~u : (u | 0x80000000u);
}

// ---------------- w preprocessing ----------------
__global__ __launch_bounds__(256) void prep_w_kernel(const float* __restrict__ w) {
    __shared__ float trf[128 * 33];
    __shared__ float sws_s[32], invs[32];
    if (blockIdx.x == 0 && blockIdx.y == 0) {
        if (threadIdx.x == 0) g_r1n = 0;
        if (threadIdx.x < NHEADS) g_r2n[threadIdx.x] = 0;
    }
    const int h = blockIdx.y, o0 = blockIdx.x * 32;
    const int tid = threadIdx.x, l = tid & 31, wid = tid >> 5;

    for (int r = wid; r < 32; r += 8) {
        float4 v = *(const float4*)(w + ((size_t)h * OD + o0 + r) * KD + l * 4);
        trf[(4*l+0)*33 + r] = v.x; trf[(4*l+1)*33 + r] = v.y;
        trf[(4*l+2)*33 + r] = v.z; trf[(4*l+3)*33 + r] = v.w;
        if (o0 >= OF) {
            float mx = fmaxf(fmaxf(fabsf(v.x), fabsf(v.y)), fmaxf(fabsf(v.z), fabsf(v.w)));
#pragma unroll
            for (int off = 16; off; off >>= 1)
                mx = fmaxf(mx, __shfl_xor_sync(0xffffffffu, mx, off));
            if (l == 0) {
                sws_s[r] = mx * (1.f / 127.f);
                invs[r]  = (mx > 0.f) ? 127.f / mx : 0.f;
            }
        }
    }
    __syncthreads();
    for (int i = tid; i < 4096; i += 256) {
        int k = i >> 5, rl = i & 31;
        g_wt[((size_t)h * KD + k) * OD + o0 + rl] = trf[k * 33 + rl];
    }
    if (o0 >= OF) {
        for (int i = tid; i < 1024; i += 256) {
            int k4 = i >> 5, rl = i & 31;
            float inv = invs[rl];
            int a0 = q8(trf[(4*k4+0)*33 + rl], inv);
            int a1 = q8(trf[(4*k4+1)*33 + rl], inv);
            int a2 = q8(trf[(4*k4+2)*33 + rl], inv);
            int a3 = q8(trf[(4*k4+3)*33 + rl], inv);
            g_wq[((size_t)h * NK4 + k4) * OI + (o0 - OF) + rl] =
                (a0 & 255) | ((a1 & 255) << 8) | ((a2 & 255) << 16) | ((a3 & 255) << 24);
        }
        if (tid < 32) g_sw[h * OI + (o0 - OF) + tid] = sws_s[tid];
    }
}

// ---------------- main hybrid kernel: 64 tok x 1 head, 256 threads, occ 2 ----------------
// 16 tx x 16 ty; thread tile = 4 tokens x (4 fp32 + 2 int8) options per iter
__global__ __launch_bounds__(NTHR, 2) void vq_hybrid_kernel(const float* __restrict__ x) {
    extern __shared__ char sm[];
    const uint32_t sb = smem_u32(sm);
    const int tid = threadIdx.x, l = tid & 31, wrp = tid >> 5;
    const int tx = tid & 15, ty = tid >> 4;
    const int t0 = blockIdx.x * TM, h = blockIdx.y;

    const float* wtsrc = g_wt + (size_t)h * KD * OD;
    const int*   wqsrc = g_wq + (size_t)h * NK4 * OI;
    const float* swsrc = g_sw + (size_t)h * OI;

    // ---- prologue: 64 tokens, staged once ----
    {
        float* stg = (float*)(sm + SM_STG);        // [64][132], 16B-aligned rows
        float* sxs = (float*)(sm + SM_SXS);
        float* inv = (float*)(sm + SM_INV);
        u64*   xs2 = (u64*)(sm + SM_XS2);
        int*   xq  = (int*)(sm + SM_XQ);
        // pass 1: each warp loads 8 token rows, row-max, stage row-major
#pragma unroll
        for (int rr = 0; rr < 8; rr++) {
            int tl = wrp * 8 + rr;                 // 0..63
            float4 v = *(const float4*)(x + (size_t)(t0 + tl) * EDIM + h * KD + l * 4);
            float mx = fmaxf(fmaxf(fabsf(v.x), fabsf(v.y)), fmaxf(fabsf(v.z), fabsf(v.w)));
#pragma unroll
            for (int off = 16; off; off >>= 1)
                mx = fmaxf(mx, __shfl_xor_sync(0xffffffffu, mx, off));
            if (l == 0) {
                sxs[tl] = mx * (1.f / 127.f);
                inv[tl] = (mx > 0.f) ? 127.f / mx : 0.f;
            }
            *(float4*)&stg[tl * 132 + l * 4] = v;
        }
        __syncthreads();
        // pass 2: transpose -> dup-packed XS2 + int8 XQ (writes outside staging)
        {
            const int t = tid & 63;                // local token
            const float invv = inv[t];
#pragma unroll
            for (int r = 0; r < 8; r++) {
                int k4 = (tid >> 6) + 4 * r;       // 0..31
                float4 f = *(const float4*)&stg[t * 132 + 4 * k4];
                xs2[(4*k4+0) * TM + t] = pack2(f.x, f.x);
                xs2[(4*k4+1) * TM + t] = pack2(f.y, f.y);
                xs2[(4*k4+2) * TM + t] = pack2(f.z, f.z);
                xs2[(4*k4+3) * TM + t] = pack2(f.w, f.w);
                int a0 = q8(f.x, invv), a1 = q8(f.y, invv);
                int a2 = q8(f.z, invv), a3 = q8(f.w, invv);
                xq[k4 * TM + t] =
                    (a0 & 255) | ((a1 & 255) << 8) | ((a2 & 255) << 16) | ((a3 & 255) << 24);
            }
        }
    }

    float fv[4]; int fi[4];
    float v1[4], v2[4], v3[4]; int i1[4], i2[4];
#pragma unroll
    for (int p = 0; p < 4; p++) {
        fv[p] = NEG_INF; fi[p] = 0;
        v1[p] = v2[p] = v3[p] = NEG_INF; i1[p] = OF; i2[p] = OF;
    }

#pragma unroll 1
    for (int it = 0; it < NIT; it++) {
        __syncthreads();   // previous chunk consumed; on it=0 guards STG->WF/WQ alias
        // WF: [k][32 pairs] u64 = 2048 16B-vectors; 8 per thread
#pragma unroll
        for (int r = 0; r < 8; r++) {
            int i = tid + NTHR * r;
            int k = i >> 4, v = i & 15;
            CP16(sb + SM_WF + k * 256 + v * 16,
                 wtsrc + (size_t)k * OD + it * CWF + v * 4);
        }
        if (it < 8) {
            // WQ: [k4][32] = 256 vectors
            int k4 = tid >> 3, s = tid & 7;
            CP16(sb + SM_WQ + k4 * 128 + s * 16,
                 wqsrc + (size_t)k4 * OI + it * CWQ + s * 4);
            if (tid < 8)
                CP16(sb + SM_SWS + tid * 16, swsrc + it * CWQ + tid * 4);
        }
        CPCOMMIT(); CPWAIT0();
        __syncthreads();

        u64 facc[4][2];
        int iacc[4][2];
#pragma unroll
        for (int p = 0; p < 4; p++) {
            facc[p][0] = facc[p][1] = 0ULL;
            iacc[p][0] = iacc[p][1] = 0;
        }

        if (it < 8) {
#pragma unroll 2
            for (int k4 = 0; k4 < NK4; k4++) {
                int4 xqv = *(const int4*)(sm + SM_XQ + (k4 * TM + ty * 4) * 4);
                int2 wqv = *(const int2*)(sm + SM_WQ + (k4 * 32 + tx * 2) * 4);
                iacc[0][0] = __dp4a(xqv.x, wqv.x, iacc[0][0]);
                iacc[0][1] = __dp4a(xqv.x, wqv.y, iacc[0][1]);
                iacc[1][0] = __dp4a(xqv.y, wqv.x, iacc[1][0]);
                iacc[1][1] = __dp4a(xqv.y, wqv.y, iacc[1][1]);
                iacc[2][0] = __dp4a(xqv.z, wqv.x, iacc[2][0]);
                iacc[2][1] = __dp4a(xqv.z, wqv.y, iacc[2][1]);
                iacc[3][0] = __dp4a(xqv.w, wqv.x, iacc[3][0]);
                iacc[3][1] = __dp4a(xqv.w, wqv.y, iacc[3][1]);
#pragma unroll
                for (int j = 0; j < 4; j++) {
                    const int k = k4 * 4 + j;
                    ulonglong2 xa = *(const ulonglong2*)(sm + SM_XS2 + (k * TM + ty * 4) * 8);
                    ulonglong2 xb = *(const ulonglong2*)(sm + SM_XS2 + (k * TM + ty * 4 + 2) * 8);
                    u64 w0 = *(const u64*)(sm + SM_WF + (k * 32 + tx) * 8);
                    u64 w1 = *(const u64*)(sm + SM_WF + (k * 32 + tx + 16) * 8);
                    facc[0][0] = ffma2(xa.x, w0, facc[0][0]);
                    facc[0][1] = ffma2(xa.x, w1, facc[0][1]);
                    facc[1][0] = ffma2(xa.y, w0, facc[1][0]);
                    facc[1][1] = ffma2(xa.y, w1, facc[1][1]);
                    facc[2][0] = ffma2(xb.x, w0, facc[2][0]);
                    facc[2][1] = ffma2(xb.x, w1, facc[2][1]);
                    facc[3][0] = ffma2(xb.y, w0, facc[3][0]);
                    facc[3][1] = ffma2(xb.y, w1, facc[3][1]);
                }
            }
        } else {
#pragma unroll 2
            for (int k4 = 0; k4 < NK4; k4++) {
#pragma unroll
                for (int j = 0; j < 4; j++) {
                    const int k = k4 * 4 + j;
                    ulonglong2 xa = *(const ulonglong2*)(sm + SM_XS2 + (k * TM + ty * 4) * 8);
                    ulonglong2 xb = *(const ulonglong2*)(sm + SM_XS2 + (k * TM + ty * 4 + 2) * 8);
                    u64 w0 = *(const u64*)(sm + SM_WF + (k * 32 + tx) * 8);
                    u64 w1 = *(const u64*)(sm + SM_WF + (k * 32 + tx + 16) * 8);
                    facc[0][0] = ffma2(xa.x, w0, facc[0][0]);
                    facc[0][1] = ffma2(xa.x, w1, facc[0][1]);
                    facc[1][0] = ffma2(xa.y, w0, facc[1][0]);
                    facc[1][1] = ffma2(xa.y, w1, facc[1][1]);
                    facc[2][0] = ffma2(xb.x, w0, facc[2][0]);
                    facc[2][1] = ffma2(xb.x, w1, facc[2][1]);
                    facc[3][0] = ffma2(xb.y, w0, facc[3][0]);
                    facc[3][1] = ffma2(xb.y, w1, facc[3][1]);
                }
            }
        }

        // fold fp32 (exact top-1; ascending option order)
#pragma unroll
        for (int p = 0; p < 4; p++) {
#pragma unroll
            for (int j = 0; j < 2; j++) {
                const int o = it * CWF + (tx + 16 * j) * 2;
                float q0, q1; unpack2(facc[p][j], q0, q1);
                if (q0 > fv[p]) { fv[p] = q0; fi[p] = o; }
                if (q1 > fv[p]) { fv[p] = q1; fi[p] = o + 1; }
            }
        }
        // fold int8 (top-3)
        if (it < 8) {
            float2 s2 = *(const float2*)(sm + SM_SWS + tx * 8);
            const int ob = OF + it * CWQ + tx * 2;
#pragma unroll
            for (int p = 0; p < 4; p++) {
#pragma unroll
                for (int u = 0; u < 2; u++) {
                    float v = (float)iacc[p][u] * (u ? s2.y : s2.x);
                    int o = ob + u;
                    if (v > v1[p]) { v3[p] = v2[p]; v2[p] = v1[p]; i2[p] = i1[p]; v1[p] = v; i1[p] = o; }
                    else if (v > v2[p]) { v3[p] = v2[p]; v2[p] = v; i2[p] = o; }
                    else if (v > v3[p]) { v3[p] = v; }
                }
            }
        }
    }

    // ---- reduce across 16 tx lanes, decide / flag ----
#pragma unroll
    for (int p = 0; p < 4; p++) {
        float a1 = v1[p], a2 = v2[p], a3 = v3[p]; int j1 = i1[p], j2 = i2[p];
        float af = fv[p]; int jf = fi[p];
#pragma unroll
        for (int off = 1; off <= 8; off <<= 1) {
            float b1 = __shfl_xor_sync(0xffffffffu, a1, off);
            float b2 = __shfl_xor_sync(0xffffffffu, a2, off);
            float b3 = __shfl_xor_sync(0xffffffffu, a3, off);
            int   k1 = __shfl_xor_sync(0xffffffffu, j1, off);
            int   k2 = __shfl_xor_sync(0xffffffffu, j2, off);
            merge3(a1, a2, a3, j1, j2, b1, b2, b3, k1, k2);
            float bf = __shfl_xor_sync(0xffffffffu, af, off);
            int   kf = __shfl_xor_sync(0xffffffffu, jf, off);
            if (bf > af || (bf == af && kf < jf)) { af = bf; jf = kf; }
        }
        if (tx == 0) {
            const int t = t0 + ty * 4 + p;
            const int pair = t * NHEADS + h;
            const float sx = ((const float*)(sm + SM_SXS))[ty * 4 + p];
            float q1 = a1 * sx, q2 = a2 * sx, q3 = a3 * sx;
            const float M = fmaxf(af, q1);
            int idx = jf;
            if (q1 <= af - TH) {
                // fp32 winner certain
            } else if (q3 >= M - TH) {
                unsigned q = atomicAdd(&g_r2n[h], 1u);
                if (q < R2CAP) { g_r2[h][q] = t; g_best[pair] = 0ULL; }
            } else if (af <= q1 - TH && q2 < M - TH) {
                idx = j1;
            } else {
                unsigned has2 = (q2 >= M - TH) ? 1u : 0u;
                unsigned qq = atomicAdd(&g_r1n, 1u);
                g_r1[qq] = make_uint2((unsigned)pair,
                                      (unsigned)jf | ((unsigned)j1 << 10) |
                                      ((unsigned)j2 << 20) | (has2 << 30));
            }
            g_idx[pair] = idx;
        }
    }
}

// ---------------- tier-1 rescue ----------------
__global__ __launch_bounds__(256) void rescue1_kernel(const float* __restrict__ x,
                                                      const float* __restrict__ w) {
    const unsigned cnt = g_r1n;
    const int l = threadIdx.x & 31;
    const int gw = (blockIdx.x * 256 + threadIdx.x) >> 5;
    for (unsigned e = gw; e < cnt; e += 2048) {
        uint2 ent = g_r1[e];
        int pair = (int)ent.x, t = pair >> 4, h = pair & 15;
        int c0 = (int)(ent.y & 0x3FF);
        int c1 = (int)((ent.y >> 10) & 0x3FF);
        int c2 = (int)((ent.y >> 20) & 0x3FF);
        bool has2 = (ent.y >> 30) != 0;
        float4 xv = ((const float4*)(x + (size_t)t * EDIM + h * KD))[l];
        float4 w0 = ((const float4*)(w + ((size_t)h * OD + c0) * KD))[l];
        float4 w1 = ((const float4*)(w + ((size_t)h * OD + c1) * KD))[l];
        float4 w2 = ((const float4*)(w + ((size_t)h * OD + c2) * KD))[l];
        float d0 = xv.x * w0.x + xv.y * w0.y + xv.z * w0.z + xv.w * w0.w;
        float d1 = xv.x * w1.x + xv.y * w1.y + xv.z * w1.z + xv.w * w1.w;
        float d2 = xv.x * w2.x + xv.y * w2.y + xv.z * w2.z + xv.w * w2.w;
#pragma unroll
        for (int off = 16; off; off >>= 1) {
            d0 += __shfl_xor_sync(0xffffffffu, d0, off);
            d1 += __shfl_xor_sync(0xffffffffu, d1, off);
            d2 += __shfl_xor_sync(0xffffffffu, d2, off);
        }
        if (l == 0) {
            float bd = d0; int bi = c0;
            if (d1 > bd || (d1 == bd && c1 < bi)) { bd = d1; bi = c1; }
            if (has2 && (d2 > bd || (d2 == bd && c2 < bi))) { bd = d2; bi = c2; }
            g_idx[pair] = bi;
        }
    }
}

// ---------------- tier-2 rescue (exact full recompute, coalesced w from g_wt) ----------------
__global__ __launch_bounds__(256) void rescue2_kernel(const float* __restrict__ x) {
    __shared__ __align__(16) float xs[128][36];
    __shared__ int toks[32];
    const int h = blockIdx.x, c = blockIdx.y, slab = blockIdx.z;
    unsigned n = g_r2n[h]; if (n > R2CAP) n = R2CAP;
    const int e0 = slab * 32;
    if (e0 >= (int)n) return;
    const int cnt = ((int)n - e0 < 32) ? ((int)n - e0) : 32;
    const int tid = threadIdx.x;

    if (tid < cnt) toks[tid] = g_r2[h][e0 + tid];
    __syncthreads();
    for (int i = tid; i < cnt * 32; i += 256) {
        int e = i >> 5, k4 = i & 31;
        float4 v = ((const float4*)(x + (size_t)toks[e] * EDIM + h * KD))[k4];
        xs[k4*4+0][e] = v.x; xs[k4*4+1][e] = v.y;
        xs[k4*4+2][e] = v.z; xs[k4*4+3][e] = v.w;
    }
    __syncthreads();

    const int ol = tid & 127, tg = tid >> 7;
    const int o = c * 128 + ol;
    const float* wcol = g_wt + (size_t)h * KD * OD + o;

    float acc[16];
#pragma unroll
    for (int u = 0; u < 16; u++) acc[u] = 0.f;

#pragma unroll 4
    for (int k = 0; k < KD; k++) {
        float wv = wcol[(size_t)k * OD];
        float4 x0 = *(const float4*)&xs[k][tg * 16];
        float4 x1 = *(const float4*)&xs[k][tg * 16 + 4];
        float4 x2 = *(const float4*)&xs[k][tg * 16 + 8];
        float4 x3 = *(const float4*)&xs[k][tg * 16 + 12];
        acc[0]  += wv * x0.x; acc[1]  += wv * x0.y; acc[2]  += wv * x0.z; acc[3]  += wv * x0.w;
        acc[4]  += wv * x1.x; acc[5]  += wv * x1.y; acc[6]  += wv * x1.z; acc[7]  += wv * x1.w;
        acc[8]  += wv * x2.x; acc[9]  += wv * x2.y; acc[10] += wv * x2.z; acc[11] += wv * x2.w;
        acc[12] += wv * x3.x; acc[13] += wv * x3.y; acc[14] += wv * x3.z; acc[15] += wv * x3.w;
    }

#pragma unroll
    for (int u = 0; u < 16; u++) {
        float v = acc[u]; int oo = o;
#pragma unroll
        for (int off = 16; off; off >>= 1) {
            float v2 = __shfl_xor_sync(0xffffffffu, v, off);
            int   o2 = __shfl_xor_sync(0xffffffffu, oo, off);
            if (v2 > v || (v2 == v && o2 < oo)) { v = v2; oo = o2; }
        }
        int te = tg * 16 + u;
        if ((tid & 31) == 0 && te < cnt) {
            u64 key = ((u64)enc_f(v) << 32) | (unsigned)(OD - 1 - oo);
            atomicMax(&g_best[toks[te] * NHEADS + h], key);
        }
    }
}

__global__ void decode_kernel() {
    const int h = blockIdx.x;
    unsigned n = g_r2n[h]; if (n > R2CAP) n = R2CAP;
    for (unsigned e = threadIdx.x; e < n; e += blockDim.x) {
        int pair = g_r2[h][e] * NHEADS + h;
        u64 key = g_best[pair];
        g_idx[pair] = (OD - 1) - (int)(key & 0xFFFFFFFFULL);
    }
}

// ---------------- gather ----------------
__global__ __launch_bounds__(256) void gather_kernel(const float* __restrict__ cb,
                                                     float* __restrict__ out) {
    const float4* cb4 = (const float4*)cb;
    float4* out4 = (float4*)out;
    int q = blockIdx.x * blockDim.x + threadIdx.x;
    int t = q >> 9, r = q & 511;
    int h = r >> 5, j = r & 31;
    int bi = g_idx[t * NHEADS + h];
    out4[(size_t)t * (EDIM / 4) + h * (KD / 4) + j] =
        cb4[((size_t)h * OD + bi) * (KD / 4) + j];
}

extern "C" void kernel_launch(void* const* d_in, const int* in_sizes, int n_in,
                              void* d_out, int out_size) {
    const float* x  = (const float*)d_in[0];
    const float* w  = (const float*)d_in[1];
    const float* cb = (const float*)d_in[2];
    // d_in[3] temperature: mathematically irrelevant in the forward pass.
    float* out = (float*)d_out;

    cudaFuncSetAttribute(vq_hybrid_kernel,
                         cudaFuncAttributeMaxDynamicSharedMemorySize, SM_TOT);

    prep_w_kernel<<<dim3(OD / 32, NHEADS), 256>>>(w);
    vq_hybrid_kernel<<<dim3(NTOK / TM, NHEADS), NTHR, SM_TOT>>>(x);
    rescue1_kernel<<<256, 256>>>(x, w);
    rescue2_kernel<<<dim3(NHEADS, 8, R2CAP / 32), 256>>>(x);
    decode_kernel<<<NHEADS, 256>>>();
    gather_kernel<<<(NTOK * EDIM / 4) / 256, 256>>>(cb, out);
}